// round 1
// baseline (speedup 1.0000x reference)
#include <cuda_runtime.h>
#include <cuda_bf16.h>
#include <cstdint>

#define HDIM 20
#define INDIM 2
#define TPB 128

typedef unsigned long long u64;

union F2u { float2 f; u64 u; };

__device__ __forceinline__ u64 pack2(float lo, float hi) {
    F2u t; t.f = make_float2(lo, hi); return t.u;
}
__device__ __forceinline__ float lo2(u64 a) { F2u t; t.u = a; return t.f.x; }
__device__ __forceinline__ float hi2(u64 a) { F2u t; t.u = a; return t.f.y; }

__device__ __forceinline__ u64 fma2(u64 a, u64 b, u64 c) {
    u64 d;
    asm("fma.rn.f32x2 %0, %1, %2, %3;" : "=l"(d) : "l"(a), "l"(b), "l"(c));
    return d;
}
__device__ __forceinline__ u64 mul2(u64 a, u64 b) {
    u64 d;
    asm("mul.rn.f32x2 %0, %1, %2;" : "=l"(d) : "l"(a), "l"(b));
    return d;
}
__device__ __forceinline__ u64 add2(u64 a, u64 b) {
    u64 d;
    asm("add.rn.f32x2 %0, %1, %2;" : "=l"(d) : "l"(a), "l"(b));
    return d;
}
__device__ __forceinline__ float ex2f(float x) {
    float y; asm("ex2.approx.f32 %0, %1;" : "=f"(y) : "f"(x)); return y;
}
__device__ __forceinline__ float rcpf(float x) {
    float y; asm("rcp.approx.f32 %0, %1;" : "=f"(y) : "f"(x)); return y;
}

// sigma(v) = 1 / (1 + 2^(-v*log2e)), elementwise on the pair
__device__ __forceinline__ u64 sigmoid2(u64 v, u64 KN, u64 ONE2) {
    u64 m = mul2(v, KN);                       // -v*log2e
    u64 e = pack2(ex2f(lo2(m)), ex2f(hi2(m))); // 2^m
    u64 s = add2(e, ONE2);
    return pack2(rcpf(lo2(s)), rcpf(hi2(s)));
}

// tanh(v) = 2 / (1 + 2^(-2v*log2e)) - 1, elementwise on the pair
__device__ __forceinline__ u64 tanh2(u64 v, u64 KN2, u64 ONE2, u64 TWO2, u64 NEG1) {
    u64 m = mul2(v, KN2);                      // -2v*log2e
    u64 e = pack2(ex2f(lo2(m)), ex2f(hi2(m)));
    u64 s = add2(e, ONE2);
    u64 r = pack2(rcpf(lo2(s)), rcpf(hi2(s)));
    return fma2(TWO2, r, NEG1);
}

__global__ __launch_bounds__(TPB, 1)
void gru_decoder_kernel(const float* __restrict__ hidden,
                        const float* __restrict__ w_ih,
                        const float* __restrict__ w_hh,
                        const float* __restrict__ b_ih,
                        const float* __restrict__ b_hh,
                        const float* __restrict__ w_l,
                        const float* __restrict__ b_l,
                        float* __restrict__ out,
                        int B, int step)
{
    // WH[j][i] = weight[i][j]; j<20 -> w_hh column j, j=20,21 -> w_ih column (j-20)
    __shared__ float WH[22][60];        // 60-float rows, 240B = 16B-aligned for float4 loads
    __shared__ float2 WLs[20];          // WLs[j] = (w_l[0][j], w_l[1][j])
    __shared__ float BIASs[80];         // [0..39] b_ih+b_hh (rz), [40..59] b_ih_n, [60..79] b_hh_n
    __shared__ float BLs[2];

    const int tid = threadIdx.x;

    for (int idx = tid; idx < 1200; idx += TPB) WH[idx % 20][idx / 20] = w_hh[idx];
    for (int idx = tid; idx < 120;  idx += TPB) WH[20 + (idx % 2)][idx / 2] = w_ih[idx];
    if (tid < 20) WLs[tid] = make_float2(w_l[tid], w_l[20 + tid]);
    if (tid < 40) BIASs[tid] = b_ih[tid] + b_hh[tid];
    if (tid < 20) { BIASs[40 + tid] = b_ih[40 + tid]; BIASs[60 + tid] = b_hh[40 + tid]; }
    if (tid < 2)  BLs[tid] = b_l[tid];
    __syncthreads();

    const int b = blockIdx.x * TPB + tid;
    if (b >= B) return;

    // h state in registers
    float h[HDIM];
    const float4* hsrc = (const float4*)(hidden + (size_t)b * HDIM);
#pragma unroll
    for (int q = 0; q < 5; ++q) {
        float4 v = hsrc[q];
        h[4 * q + 0] = v.x; h[4 * q + 1] = v.y; h[4 * q + 2] = v.z; h[4 * q + 3] = v.w;
    }

    const u64 KN   = pack2(-1.4426950408889634f, -1.4426950408889634f);
    const u64 KN2  = pack2(-2.8853900817779268f, -2.8853900817779268f);
    const u64 ONE2 = pack2(1.0f, 1.0f);
    const u64 TWO2 = pack2(2.0f, 2.0f);
    const u64 NEG1 = pack2(-1.0f, -1.0f);

    float x0 = 0.0f, x1 = 0.0f;
    const float bl0 = BLs[0], bl1 = BLs[1];
    float* outb = out + (size_t)b * step * 2;

#pragma unroll 1
    for (int t = 0; t < step; ++t) {
        u64 rz[20], in_[10], hn[10];

        const float2* bp = (const float2*)BIASs;
#pragma unroll
        for (int p = 0; p < 20; ++p) { F2u v; v.f = bp[p];      rz[p]  = v.u; }
#pragma unroll
        for (int p = 0; p < 10; ++p) { F2u v; v.f = bp[20 + p]; in_[p] = v.u; }
#pragma unroll
        for (int p = 0; p < 10; ++p) { F2u v; v.f = bp[30 + p]; hn[p]  = v.u; }

        // gi: x contribution (K=2). rows 0..39 -> rz, rows 40..59 -> inn
#pragma unroll
        for (int jj = 0; jj < 2; ++jj) {
            const float xv = jj ? x1 : x0;
            const u64 xd = pack2(xv, xv);
            const float4* row = (const float4*)&WH[20 + jj][0];
#pragma unroll
            for (int m = 0; m < 10; ++m) {
                float4 w = row[m];
                rz[2 * m + 0] = fma2(pack2(w.x, w.y), xd, rz[2 * m + 0]);
                rz[2 * m + 1] = fma2(pack2(w.z, w.w), xd, rz[2 * m + 1]);
            }
#pragma unroll
            for (int m = 10; m < 15; ++m) {
                float4 w = row[m];
                in_[2 * m - 20] = fma2(pack2(w.x, w.y), xd, in_[2 * m - 20]);
                in_[2 * m - 19] = fma2(pack2(w.z, w.w), xd, in_[2 * m - 19]);
            }
        }

        // gh: h contribution (K=20). rows 0..39 -> rz, rows 40..59 -> hn
#pragma unroll
        for (int j = 0; j < HDIM; ++j) {
            const u64 hd = pack2(h[j], h[j]);
            const float4* row = (const float4*)&WH[j][0];
#pragma unroll
            for (int m = 0; m < 10; ++m) {
                float4 w = row[m];
                rz[2 * m + 0] = fma2(pack2(w.x, w.y), hd, rz[2 * m + 0]);
                rz[2 * m + 1] = fma2(pack2(w.z, w.w), hd, rz[2 * m + 1]);
            }
#pragma unroll
            for (int m = 10; m < 15; ++m) {
                float4 w = row[m];
                hn[2 * m - 20] = fma2(pack2(w.x, w.y), hd, hn[2 * m - 20]);
                hn[2 * m - 19] = fma2(pack2(w.z, w.w), hd, hn[2 * m - 19]);
            }
        }

        // gates + state update, pairwise over h dims (2p, 2p+1)
#pragma unroll
        for (int p = 0; p < 10; ++p) {
            const u64 r = sigmoid2(rz[p],      KN, ONE2);
            const u64 z = sigmoid2(rz[10 + p], KN, ONE2);
            const u64 n = tanh2(fma2(r, hn[p], in_[p]), KN2, ONE2, TWO2, NEG1);
            const u64 hp = pack2(h[2 * p], h[2 * p + 1]);
            // h_new = (1-z)*n + z*h = (z*h + n) - z*n
            const u64 t1 = fma2(z, hp, n);
            const u64 zn = z ^ 0x8000000080000000ULL;   // -z (sign flip, alu pipe)
            const u64 hnew = fma2(zn, n, t1);
            h[2 * p]     = lo2(hnew);
            h[2 * p + 1] = hi2(hnew);
        }

        // y = W_l @ h_new + b_l
        float y0 = bl0, y1 = bl1;
#pragma unroll
        for (int j = 0; j < HDIM; ++j) {
            float2 w = WLs[j];
            y0 = fmaf(w.x, h[j], y0);
            y1 = fmaf(w.y, h[j], y1);
        }

        // output is time-reversed: y_t -> slot (step-1-t)
        *(float2*)(outb + (size_t)(step - 1 - t) * 2) = make_float2(y0, y1);
        x0 = y0; x1 = y1;
    }
}

extern "C" void kernel_launch(void* const* d_in, const int* in_sizes, int n_in,
                              void* d_out, int out_size) {
    const float* hidden = (const float*)d_in[0];
    const float* w_ih   = (const float*)d_in[1];
    const float* w_hh   = (const float*)d_in[2];
    const float* b_ih   = (const float*)d_in[3];
    const float* b_hh   = (const float*)d_in[4];
    const float* w_l    = (const float*)d_in[5];
    const float* b_l    = (const float*)d_in[6];

    const int B = in_sizes[0] / HDIM;           // hidden is (1, B, 20)
    const int step = out_size / (2 * B);        // out is (B, step, 2)

    const int grid = (B + TPB - 1) / TPB;
    gru_decoder_kernel<<<grid, TPB>>>(hidden, w_ih, w_hh, b_ih, b_hh, w_l, b_l,
                                      (float*)d_out, B, step);
}

// round 2
// speedup vs baseline: 9.8757x; 9.8757x over previous
#include <cuda_runtime.h>
#include <cuda_bf16.h>
#include <cstdint>

#define HDIM 20
#define TPB 128

typedef unsigned long long u64;

union F2u { float2 f; u64 u; };
union F4u { float4 f; u64 u[2]; };

__device__ __forceinline__ u64 pack2(float lo, float hi) {
    F2u t; t.f = make_float2(lo, hi); return t.u;
}
__device__ __forceinline__ float lo2(u64 a) { F2u t; t.u = a; return t.f.x; }
__device__ __forceinline__ float hi2(u64 a) { F2u t; t.u = a; return t.f.y; }

__device__ __forceinline__ u64 fma2(u64 a, u64 b, u64 c) {
    u64 d;
    asm("fma.rn.f32x2 %0, %1, %2, %3;" : "=l"(d) : "l"(a), "l"(b), "l"(c));
    return d;
}
__device__ __forceinline__ u64 add2(u64 a, u64 b) {
    u64 d;
    asm("add.rn.f32x2 %0, %1, %2;" : "=l"(d) : "l"(a), "l"(b));
    return d;
}
__device__ __forceinline__ float ex2f(float x) {
    float y; asm("ex2.approx.f32 %0, %1;" : "=f"(y) : "f"(x)); return y;
}
__device__ __forceinline__ float rcpf(float x) {
    float y; asm("rcp.approx.f32 %0, %1;" : "=f"(y) : "f"(x)); return y;
}
__device__ __forceinline__ u64 ex2x2(u64 a) { return pack2(ex2f(lo2(a)), ex2f(hi2(a))); }
__device__ __forceinline__ u64 rcp2(u64 a)  { return pack2(rcpf(lo2(a)), rcpf(hi2(a))); }

// weight pre-scales: sigmoid(v) = rcp(1 + ex2(C1*v)), tanh(v) = 2*rcp(1 + ex2(C2*v)) - 1
#define C1 (-1.4426950408889634f)
#define C2 (-2.8853900817779268f)

__global__ __launch_bounds__(TPB, 4)
void gru_decoder_kernel(const float* __restrict__ hidden,
                        const float* __restrict__ w_ih,
                        const float* __restrict__ w_hh,
                        const float* __restrict__ b_ih,
                        const float* __restrict__ b_hh,
                        const float* __restrict__ w_l,
                        const float* __restrict__ b_l,
                        float* __restrict__ out,
                        int B, int step)
{
    // WP[p][j][0..5] = scaled weights for output pair p, input dim j:
    //   [0,1] = C1*W[2p][j],   C1*W[2p+1][j]      (r rows)
    //   [2,3] = C1*W[20+2p][j],C1*W[21+2p][j]     (z rows)
    //   [4,5] = C2*W[40+2p][j],C2*W[41+2p][j]     (n rows)
    // where W[i][j] = w_hh[i*20+j] for j<20, w_ih[i*2+(j-20)] for j=20,21
    __shared__ __align__(16) float WP[10][22][8];
    __shared__ float2 BR[10], BZ[10], BIN[10], BHN[10];
    __shared__ float2 WLs[20];
    __shared__ float2 BLs;
    __shared__ u64 HNEW[TPB][11];   // stride 11 u64 = 22 words: conflict-free LDS.64

    const int tid = threadIdx.x;

    for (int idx = tid; idx < 10 * 22 * 6; idx += TPB) {
        int p = idx / (22 * 6);
        int r = idx % (22 * 6);
        int j = r / 6;
        int c = r % 6;
        int row = (c < 2) ? (2 * p + c) : (c < 4) ? (20 + 2 * p + (c - 2)) : (40 + 2 * p + (c - 4));
        float w = (j < 20) ? w_hh[row * 20 + j] : w_ih[row * 2 + (j - 20)];
        WP[p][j][c] = w * ((c < 4) ? C1 : C2);
    }
    if (tid < 10) {
        int p = tid;
        BR[p]  = make_float2(C1 * (b_ih[2*p]      + b_hh[2*p]),
                             C1 * (b_ih[2*p+1]    + b_hh[2*p+1]));
        BZ[p]  = make_float2(C1 * (b_ih[20+2*p]   + b_hh[20+2*p]),
                             C1 * (b_ih[21+2*p]   + b_hh[21+2*p]));
        BIN[p] = make_float2(C2 * b_ih[40+2*p],  C2 * b_ih[41+2*p]);
        BHN[p] = make_float2(C2 * b_hh[40+2*p],  C2 * b_hh[41+2*p]);
    }
    if (tid < 20) WLs[tid] = make_float2(w_l[tid], w_l[20 + tid]);
    if (tid == 0) BLs = make_float2(b_l[0], b_l[1]);
    __syncthreads();

    const int b = blockIdx.x * TPB + tid;
    if (b >= B) return;

    // h state: hd[j] = (h[j], h[j]) duplicated pairs; HNEW[tid][p] = (h[2p], h[2p+1])
    u64 hd[HDIM];
    {
        const float4* hsrc = (const float4*)(hidden + (size_t)b * HDIM);
#pragma unroll
        for (int q = 0; q < 5; ++q) {
            float4 v = hsrc[q];
            hd[4*q+0] = pack2(v.x, v.x);
            hd[4*q+1] = pack2(v.y, v.y);
            hd[4*q+2] = pack2(v.z, v.z);
            hd[4*q+3] = pack2(v.w, v.w);
            HNEW[tid][2*q]   = pack2(v.x, v.y);
            HNEW[tid][2*q+1] = pack2(v.z, v.w);
        }
    }

    const u64 ONE2 = pack2(1.0f, 1.0f);
    const u64 TWO2 = pack2(2.0f, 2.0f);
    const u64 NEG1 = pack2(-1.0f, -1.0f);

    u64 xd0 = 0, xd1 = 0;   // (0.0, 0.0) pairs
    F2u blv; blv.f = BLs;
    float* outb = out + (size_t)b * step * 2;
    u64* myh = &HNEW[tid][0];

#pragma unroll 1
    for (int t = 0; t < step; ++t) {
#pragma unroll 1
        for (int p = 0; p < 10; ++p) {
            F2u tb;
            tb.f = BR[p];  u64 acc_r  = tb.u;
            tb.f = BZ[p];  u64 acc_z  = tb.u;
            tb.f = BIN[p]; u64 acc_in = tb.u;
            tb.f = BHN[p]; u64 acc_hn = tb.u;

            const float* wp = &WP[p][0][0];
#pragma unroll
            for (int j = 0; j < HDIM; ++j) {
                F4u a; a.f = *(const float4*)(wp + j * 8);
                F2u n; n.f = *(const float2*)(wp + j * 8 + 4);
                acc_r  = fma2(a.u[0], hd[j], acc_r);
                acc_z  = fma2(a.u[1], hd[j], acc_z);
                acc_hn = fma2(n.u,    hd[j], acc_hn);
            }
            // x contribution (j = 20, 21): n-rows go to acc_in (not multiplied by r)
#pragma unroll
            for (int jj = 0; jj < 2; ++jj) {
                const u64 xd = jj ? xd1 : xd0;
                F4u a; a.f = *(const float4*)(wp + (HDIM + jj) * 8);
                F2u n; n.f = *(const float2*)(wp + (HDIM + jj) * 8 + 4);
                acc_r  = fma2(a.u[0], xd, acc_r);
                acc_z  = fma2(a.u[1], xd, acc_z);
                acc_in = fma2(n.u,    xd, acc_in);
            }

            // gates (accumulators pre-scaled by C1 / C2)
            const u64 r = rcp2(add2(ex2x2(acc_r), ONE2));
            const u64 z = rcp2(add2(ex2x2(acc_z), ONE2));
            const u64 s = fma2(r, acc_hn, acc_in);
            const u64 n = fma2(TWO2, rcp2(add2(ex2x2(s), ONE2)), NEG1);

            const u64 hp = myh[p];                        // previous (h[2p], h[2p+1])
            const u64 t1 = fma2(z, hp, n);                // z*h + n
            const u64 zn = z ^ 0x8000000080000000ULL;     // -z
            myh[p] = fma2(zn, n, t1);                     // (z*h + n) - z*n
        }

        // refresh dup pairs + y = W_l @ h_new + b_l (fully unrolled: static hd indices)
        u64 yp = blv.u;
#pragma unroll
        for (int p = 0; p < 10; ++p) {
            const u64 hpair = myh[p];
            const float h0 = lo2(hpair), h1 = hi2(hpair);
            hd[2*p]   = pack2(h0, h0);
            hd[2*p+1] = pack2(h1, h1);
            F2u w0; w0.f = WLs[2*p];
            F2u w1; w1.f = WLs[2*p+1];
            yp = fma2(w0.u, hd[2*p],   yp);
            yp = fma2(w1.u, hd[2*p+1], yp);
        }

        // output time-reversed: y_t -> slot (step-1-t)
        F2u yo; yo.u = yp;
        *(float2*)(outb + (size_t)(step - 1 - t) * 2) = yo.f;
        xd0 = pack2(lo2(yp), lo2(yp));
        xd1 = pack2(hi2(yp), hi2(yp));
    }
}

extern "C" void kernel_launch(void* const* d_in, const int* in_sizes, int n_in,
                              void* d_out, int out_size) {
    const float* hidden = (const float*)d_in[0];
    const float* w_ih   = (const float*)d_in[1];
    const float* w_hh   = (const float*)d_in[2];
    const float* b_ih   = (const float*)d_in[3];
    const float* b_hh   = (const float*)d_in[4];
    const float* w_l    = (const float*)d_in[5];
    const float* b_l    = (const float*)d_in[6];

    const int B = in_sizes[0] / HDIM;        // hidden is (1, B, 20)
    const int step = out_size / (2 * B);     // out is (B, step, 2)

    const int grid = (B + TPB - 1) / TPB;
    gru_decoder_kernel<<<grid, TPB>>>(hidden, w_ih, w_hh, b_ih, b_hh, w_l, b_l,
                                      (float*)d_out, B, step);
}

// round 3
// speedup vs baseline: 10.9182x; 1.1056x over previous
#include <cuda_runtime.h>
#include <cuda_bf16.h>
#include <cstdint>

#define HDIM 20
#define TPB 64

typedef unsigned long long u64;

union F2u { float2 f; u64 u; };
union F4u { float4 f; u64 u[2]; };

__device__ __forceinline__ u64 pack2(float lo, float hi) {
    F2u t; t.f = make_float2(lo, hi); return t.u;
}
__device__ __forceinline__ float lo2(u64 a) { F2u t; t.u = a; return t.f.x; }
__device__ __forceinline__ float hi2(u64 a) { F2u t; t.u = a; return t.f.y; }

__device__ __forceinline__ u64 fma2(u64 a, u64 b, u64 c) {
    u64 d;
    asm("fma.rn.f32x2 %0, %1, %2, %3;" : "=l"(d) : "l"(a), "l"(b), "l"(c));
    return d;
}
__device__ __forceinline__ u64 add2(u64 a, u64 b) {
    u64 d;
    asm("add.rn.f32x2 %0, %1, %2;" : "=l"(d) : "l"(a), "l"(b));
    return d;
}
__device__ __forceinline__ float ex2f(float x) {
    float y; asm("ex2.approx.f32 %0, %1;" : "=f"(y) : "f"(x)); return y;
}
__device__ __forceinline__ float rcpf(float x) {
    float y; asm("rcp.approx.f32 %0, %1;" : "=f"(y) : "f"(x)); return y;
}
__device__ __forceinline__ u64 ex2x2(u64 a) { return pack2(ex2f(lo2(a)), ex2f(hi2(a))); }
__device__ __forceinline__ u64 rcp2(u64 a)  { return pack2(rcpf(lo2(a)), rcpf(hi2(a))); }

// pre-scales: sigmoid(v) = rcp(1 + ex2(C1*v)), tanh(v) = 2*rcp(1 + ex2(C2*v)) - 1
#define C1 (-1.4426950408889634f)
#define C2 (-2.8853900817779268f)

__global__ __launch_bounds__(TPB, 8)
void gru_decoder_kernel(const float* __restrict__ hidden,
                        const float* __restrict__ w_ih,
                        const float* __restrict__ w_hh,
                        const float* __restrict__ b_ih,
                        const float* __restrict__ b_hh,
                        const float* __restrict__ w_l,
                        const float* __restrict__ b_l,
                        float* __restrict__ out,
                        int B, int step)
{
    // Extended weight matrix W[i][j], i in [0,60), j in [0,22):
    //   j<20: w_hh[i*20+j]; j=20,21: w_ih[i*2+(j-20)] (x columns)
    // WP[p][jj][12] for gate-pair p, j-pair jj (j0=2jj, j1=2jj+1; jj=10 -> x pair):
    //   [0..3]  = C1*{W[2p][j0], W[2p+1][j0], W[20+2p][j0], W[21+2p][j0]}   (rz, j0)
    //   [4..7]  = C2*{W[40+2p][j0], W[41+2p][j0], W[40+2p][j1], W[41+2p][j1]} (n, j0&j1)
    //   [8..11] = C1*{W[2p][j1], W[2p+1][j1], W[20+2p][j1], W[21+2p][j1]}   (rz, j1)
    __shared__ __align__(16) float WP[10][11][12];
    __shared__ __align__(16) float BP[10][8];
    __shared__ __align__(16) float WL4[10][4];
    __shared__ float BL2[2];

    const int tid = threadIdx.x;

    for (int idx = tid; idx < 10 * 11 * 12; idx += TPB) {
        int p  = idx / 132;
        int r  = idx % 132;
        int jj = r / 12;
        int c  = r % 12;
        int j0 = 2 * jj, j1 = 2 * jj + 1;
        int row, jcol; float sc;
        if (c < 4)      { row = (c < 2) ? (2*p + c) : (20 + 2*p + (c - 2)); jcol = j0; sc = C1; }
        else if (c < 8) { row = 40 + 2*p + (c & 1); jcol = (c < 6) ? j0 : j1; sc = C2; }
        else            { int cc = c - 8;
                          row = (cc < 2) ? (2*p + cc) : (20 + 2*p + (cc - 2)); jcol = j1; sc = C1; }
        float w = (jcol < 20) ? w_hh[row * 20 + jcol] : w_ih[row * 2 + (jcol - 20)];
        WP[p][jj][c] = w * sc;
    }
    if (tid < 10) {
        int p = tid;
        BP[p][0] = C1 * (b_ih[2*p]      + b_hh[2*p]);
        BP[p][1] = C1 * (b_ih[2*p + 1]  + b_hh[2*p + 1]);
        BP[p][2] = C1 * (b_ih[20 + 2*p] + b_hh[20 + 2*p]);
        BP[p][3] = C1 * (b_ih[21 + 2*p] + b_hh[21 + 2*p]);
        BP[p][4] = C2 * b_ih[40 + 2*p];
        BP[p][5] = C2 * b_ih[41 + 2*p];
        BP[p][6] = C2 * b_hh[40 + 2*p];
        BP[p][7] = C2 * b_hh[41 + 2*p];
        // y weights: (w_l[0][2p], w_l[1][2p], w_l[0][2p+1], w_l[1][2p+1])
        WL4[p][0] = w_l[2*p];
        WL4[p][1] = w_l[20 + 2*p];
        WL4[p][2] = w_l[2*p + 1];
        WL4[p][3] = w_l[21 + 2*p];
    }
    if (tid < 2) BL2[tid] = b_l[tid];
    __syncthreads();

    const int gtid = blockIdx.x * TPB + tid;
    const int e    = gtid >> 1;       // batch element
    const int role = gtid & 1;        // 0 -> gate pairs 0..4, 1 -> 5..9
    if (e >= B) return;
    const int pbase = 5 * role;

    // hd[j] = (h[j], h[j]) duplicated pairs; hq[q] = (h[2p], h[2p+1]) for own p = pbase+q
    u64 hd[HDIM];
    u64 hq[5];
    {
        float hv[HDIM];
        const float4* hsrc = (const float4*)(hidden + (size_t)e * HDIM);
#pragma unroll
        for (int qq = 0; qq < 5; ++qq) {
            float4 v = hsrc[qq];
            hv[4*qq+0] = v.x; hv[4*qq+1] = v.y; hv[4*qq+2] = v.z; hv[4*qq+3] = v.w;
        }
#pragma unroll
        for (int j = 0; j < HDIM; ++j) hd[j] = pack2(hv[j], hv[j]);
#pragma unroll
        for (int q = 0; q < 5; ++q) {
            u64 a = pack2(hv[2*q],      hv[2*q + 1]);
            u64 b2 = pack2(hv[10 + 2*q], hv[11 + 2*q]);
            hq[q] = role ? b2 : a;
        }
    }

    const u64 ONE2 = pack2(1.0f, 1.0f);
    const u64 TWO2 = pack2(2.0f, 2.0f);
    const u64 NEG1 = pack2(-1.0f, -1.0f);

    const float yb0 = role ? 0.0f : BL2[0];
    const float yb1 = role ? 0.0f : BL2[1];

    u64 xd0 = 0, xd1 = 0;   // duplicated x pairs (x starts at 0)
    float* outb = out + (size_t)e * step * 2;

    const float* wpb = &WP[pbase][0][0];
    const float* bpb = &BP[pbase][0];
    const float* wlb = &WL4[pbase][0];

#pragma unroll 1
    for (int t = 0; t < step; ++t) {
        u64 hnq[5];

#pragma unroll
        for (int q = 0; q < 5; ++q) {
            const float* wq = wpb + q * 132;
            F4u b0; b0.f = *(const float4*)(bpb + q * 8);
            F4u b1; b1.f = *(const float4*)(bpb + q * 8 + 4);
            u64 acc_r  = b0.u[0];
            u64 acc_z  = b0.u[1];
            u64 acc_in = b1.u[0];
            u64 acc_hn = b1.u[1];

#pragma unroll
            for (int jj = 0; jj < 11; ++jj) {
                F4u A0; A0.f = *(const float4*)(wq + jj * 12);
                F4u Nn; Nn.f = *(const float4*)(wq + jj * 12 + 4);
                F4u A1; A1.f = *(const float4*)(wq + jj * 12 + 8);
                const u64 h0 = (jj < 10) ? hd[2*jj]     : xd0;
                const u64 h1 = (jj < 10) ? hd[2*jj + 1] : xd1;
                acc_r = fma2(A0.u[0], h0, acc_r);
                acc_z = fma2(A0.u[1], h0, acc_z);
                if (jj < 10) {
                    acc_hn = fma2(Nn.u[0], h0, acc_hn);
                    acc_hn = fma2(Nn.u[1], h1, acc_hn);
                } else {
                    acc_in = fma2(Nn.u[0], h0, acc_in);   // x part of n goes to inn
                    acc_in = fma2(Nn.u[1], h1, acc_in);
                }
                acc_r = fma2(A1.u[0], h1, acc_r);
                acc_z = fma2(A1.u[1], h1, acc_z);
            }

            // gates (accumulators pre-scaled by C1 / C2)
            const u64 r = rcp2(add2(ex2x2(acc_r), ONE2));
            const u64 z = rcp2(add2(ex2x2(acc_z), ONE2));
            const u64 s = fma2(r, acc_hn, acc_in);
            const u64 n = fma2(TWO2, rcp2(add2(ex2x2(s), ONE2)), NEG1);

            const u64 hp = hq[q];                         // previous (h[2p], h[2p+1])
            const u64 t1 = fma2(z, hp, n);                // z*h + n
            const u64 zn = z ^ 0x8000000080000000ULL;     // -z
            hnq[q] = fma2(zn, n, t1);                     // (z*h + n) - z*n
        }

        // partial y over own 10 dims (scalar FFMA, no dup needed)
        float y0 = yb0, y1 = yb1;
#pragma unroll
        for (int q = 0; q < 5; ++q) {
            float4 wl = *(const float4*)(wlb + q * 4);
            const float ha = lo2(hnq[q]), hb = hi2(hnq[q]);
            y0 = fmaf(wl.x, ha, y0);
            y1 = fmaf(wl.y, ha, y1);
            y0 = fmaf(wl.z, hb, y0);
            y1 = fmaf(wl.w, hb, y1);
        }
        y0 += __shfl_xor_sync(0xFFFFFFFFu, y0, 1);
        y1 += __shfl_xor_sync(0xFFFFFFFFu, y1, 1);

        // exchange h pairs with partner, rebuild duplicated hd
#pragma unroll
        for (int q = 0; q < 5; ++q) {
            const u64 pq = __shfl_xor_sync(0xFFFFFFFFu, hnq[q], 1);
            const u64 low  = role ? pq      : hnq[q];   // dims 2q, 2q+1
            const u64 high = role ? hnq[q]  : pq;       // dims 10+2q, 11+2q
            hd[2*q]      = pack2(lo2(low),  lo2(low));
            hd[2*q + 1]  = pack2(hi2(low),  hi2(low));
            hd[10 + 2*q] = pack2(lo2(high), lo2(high));
            hd[11 + 2*q] = pack2(hi2(high), hi2(high));
            hq[q] = hnq[q];
        }

        // output time-reversed: y_t -> slot (step-1-t); one store per element
        if (!role)
            *(float2*)(outb + (size_t)(step - 1 - t) * 2) = make_float2(y0, y1);
        xd0 = pack2(y0, y0);
        xd1 = pack2(y1, y1);
    }
}

extern "C" void kernel_launch(void* const* d_in, const int* in_sizes, int n_in,
                              void* d_out, int out_size) {
    const float* hidden = (const float*)d_in[0];
    const float* w_ih   = (const float*)d_in[1];
    const float* w_hh   = (const float*)d_in[2];
    const float* b_ih   = (const float*)d_in[3];
    const float* b_hh   = (const float*)d_in[4];
    const float* w_l    = (const float*)d_in[5];
    const float* b_l    = (const float*)d_in[6];

    const int B = in_sizes[0] / HDIM;        // hidden is (1, B, 20)
    const int step = out_size / (2 * B);     // out is (B, step, 2)

    const int nthreads = 2 * B;              // 2 threads per batch element
    const int grid = (nthreads + TPB - 1) / TPB;
    gru_decoder_kernel<<<grid, TPB>>>(hidden, w_ih, w_hh, b_ih, b_hh, w_l, b_l,
                                      (float*)d_out, B, step);
}